// round 6
// baseline (speedup 1.0000x reference)
#include <cuda_runtime.h>
#include <cstddef>

#define B_ 256
#define S_ 200
#define E_ 512
#define H_ 512

// ---- scratch (no allocations allowed) ----
__device__ float g_P[(size_t)B_ * S_ * H_];   // 104 MB: P[t][b][h]
__device__ float g_h[2][B_ * H_];             // double-buffered hidden state
__device__ float g_pool[B_ * H_];             // time-mean of h
__device__ unsigned int g_bars[16];           // per-M-group barrier counters

typedef unsigned long long u64;

__device__ __forceinline__ void fma2(u64 &c, u64 a, u64 b) {
    asm("fma.rn.f32x2 %0, %1, %2, %3;" : "=l"(c) : "l"(a), "l"(b), "l"(c));
}
__device__ __forceinline__ u64 splat2(float a) {
    u64 r; asm("mov.b64 %0, {%1, %1};" : "=l"(r) : "f"(a)); return r;
}
__device__ __forceinline__ float2 u2f(u64 v) {
    float2 r; asm("mov.b64 {%0, %1}, %2;" : "=f"(r.x), "=f"(r.y) : "l"(v)); return r;
}

// ============================================================================
// Kernel A: P = gather(emb, x) @ Wxh + (bxh + bhh)   (unchanged from R5)
// ============================================================================
#define PAST 36
#define PC_SMEM ((2 * 64 * PAST + 2 * 32 * 128) * 4)  // 51200 B

__global__ __launch_bounds__(256, 2) void precompute_kernel(
    const int* __restrict__ x, const float* __restrict__ emb,
    const float* __restrict__ Wxh, const float* __restrict__ bxh,
    const float* __restrict__ bhh)
{
    extern __shared__ float psm[];
    float* AsB = psm;                    // [2][64][PAST]
    float* WsB = psm + 2 * 64 * PAST;    // [2][32][128]

    const int n0 = blockIdx.x * 128;
    const int m0 = blockIdx.y * 64;
    const int t  = threadIdx.x;
    const int w  = t >> 5, l = t & 31;
    const int row0 = w * 8;
    const int c4 = 4 * l;

    const int arow  = t >> 3;
    const int aslot = (t & 7) * 4;
    const size_t e0 = (size_t)x[m0 + arow] * E_;
    const size_t e1 = (size_t)x[m0 + arow + 32] * E_;
    const int wrow = t >> 5;
    const int wcol = (t & 31) * 4;

    u64 acc[8][2];
#pragma unroll
    for (int i = 0; i < 8; i++) { acc[i][0] = 0ull; acc[i][1] = 0ull; }

    float4 pa0, pa1, pw0, pw1, pw2, pw3;
    pa0 = *(const float4*)&emb[e0 + aslot];
    pa1 = *(const float4*)&emb[e1 + aslot];
    pw0 = *(const float4*)&Wxh[(size_t)(0  + wrow) * H_ + n0 + wcol];
    pw1 = *(const float4*)&Wxh[(size_t)(8  + wrow) * H_ + n0 + wcol];
    pw2 = *(const float4*)&Wxh[(size_t)(16 + wrow) * H_ + n0 + wcol];
    pw3 = *(const float4*)&Wxh[(size_t)(24 + wrow) * H_ + n0 + wcol];
    *(float4*)&AsB[arow * PAST + aslot]        = pa0;
    *(float4*)&AsB[(arow + 32) * PAST + aslot] = pa1;
    *(float4*)&WsB[(0  + wrow) * 128 + wcol] = pw0;
    *(float4*)&WsB[(8  + wrow) * 128 + wcol] = pw1;
    *(float4*)&WsB[(16 + wrow) * 128 + wcol] = pw2;
    *(float4*)&WsB[(24 + wrow) * 128 + wcol] = pw3;
    __syncthreads();

#pragma unroll 1
    for (int ch = 0; ch < 16; ch++) {
        if (ch < 15) {
            const int kn = (ch + 1) * 32;
            pa0 = *(const float4*)&emb[e0 + kn + aslot];
            pa1 = *(const float4*)&emb[e1 + kn + aslot];
            pw0 = *(const float4*)&Wxh[(size_t)(kn + wrow) * H_ + n0 + wcol];
            pw1 = *(const float4*)&Wxh[(size_t)(kn + 8  + wrow) * H_ + n0 + wcol];
            pw2 = *(const float4*)&Wxh[(size_t)(kn + 16 + wrow) * H_ + n0 + wcol];
            pw3 = *(const float4*)&Wxh[(size_t)(kn + 24 + wrow) * H_ + n0 + wcol];
        }
        const float* Ab = AsB + (ch & 1) * (64 * PAST);
        const float* Wb = WsB + (ch & 1) * (32 * 128);

#pragma unroll
        for (int kg = 0; kg < 8; kg++) {
            float4 a0 = *(const float4*)&Ab[(row0 + 0) * PAST + kg * 4];
            float4 a1 = *(const float4*)&Ab[(row0 + 1) * PAST + kg * 4];
            float4 a2 = *(const float4*)&Ab[(row0 + 2) * PAST + kg * 4];
            float4 a3 = *(const float4*)&Ab[(row0 + 3) * PAST + kg * 4];
            float4 a4 = *(const float4*)&Ab[(row0 + 4) * PAST + kg * 4];
            float4 a5 = *(const float4*)&Ab[(row0 + 5) * PAST + kg * 4];
            float4 a6 = *(const float4*)&Ab[(row0 + 6) * PAST + kg * 4];
            float4 a7 = *(const float4*)&Ab[(row0 + 7) * PAST + kg * 4];
#define PKJ(j, comp) {                                              \
            const u64* wp = (const u64*)&Wb[(kg * 4 + (j)) * 128 + c4]; \
            u64 w01 = wp[0], w23 = wp[1];                           \
            fma2(acc[0][0], splat2(a0.comp), w01); fma2(acc[0][1], splat2(a0.comp), w23); \
            fma2(acc[1][0], splat2(a1.comp), w01); fma2(acc[1][1], splat2(a1.comp), w23); \
            fma2(acc[2][0], splat2(a2.comp), w01); fma2(acc[2][1], splat2(a2.comp), w23); \
            fma2(acc[3][0], splat2(a3.comp), w01); fma2(acc[3][1], splat2(a3.comp), w23); \
            fma2(acc[4][0], splat2(a4.comp), w01); fma2(acc[4][1], splat2(a4.comp), w23); \
            fma2(acc[5][0], splat2(a5.comp), w01); fma2(acc[5][1], splat2(a5.comp), w23); \
            fma2(acc[6][0], splat2(a6.comp), w01); fma2(acc[6][1], splat2(a6.comp), w23); \
            fma2(acc[7][0], splat2(a7.comp), w01); fma2(acc[7][1], splat2(a7.comp), w23); }
            PKJ(0, x) PKJ(1, y) PKJ(2, z) PKJ(3, w)
#undef PKJ
        }

        if (ch < 15) {
            float* An = AsB + ((ch + 1) & 1) * (64 * PAST);
            float* Wn = WsB + ((ch + 1) & 1) * (32 * 128);
            *(float4*)&An[arow * PAST + aslot]        = pa0;
            *(float4*)&An[(arow + 32) * PAST + aslot] = pa1;
            *(float4*)&Wn[(0  + wrow) * 128 + wcol] = pw0;
            *(float4*)&Wn[(8  + wrow) * 128 + wcol] = pw1;
            *(float4*)&Wn[(16 + wrow) * 128 + wcol] = pw2;
            *(float4*)&Wn[(24 + wrow) * 128 + wcol] = pw3;
            __syncthreads();
        }
    }

    float4 bxv = *(const float4*)&bxh[n0 + c4];
    float4 bhv = *(const float4*)&bhh[n0 + c4];
    const float b0 = bxv.x + bhv.x, b1 = bxv.y + bhv.y;
    const float b2 = bxv.z + bhv.z, b3 = bxv.w + bhv.w;
#pragma unroll
    for (int i = 0; i < 8; i++) {
        float2 v0 = u2f(acc[i][0]);
        float2 v1 = u2f(acc[i][1]);
        float4 o; o.x = v0.x + b0; o.y = v0.y + b1; o.z = v1.x + b2; o.w = v1.y + b3;
        int m = m0 + row0 + i;
        int bb = m / S_;
        int tt = m - bb * S_;
        *(float4*)&g_P[((size_t)tt * B_ + bb) * H_ + n0 + c4] = o;
    }
}

// ============================================================================
// Kernel B: persistent recurrent kernel — NEW thread tile.
// 128 CTAs = 16 M-groups x 8 N-tiles; Whh slice stationary in smem.
// Warp w: half-warp 0 (lanes 0-15) rows 4w,4w+1; half-warp 1 rows 4w+2,4w+3.
// Lane column: c4 = 4*(lane&15) -> W LDS.128 is half-warp-duplicated (2 wf),
// each W fetch feeds 4 FFMA2. Per 4k/warp: 10 wf vs 32 FMA cycles.
// ============================================================================
#define ASTRIDE 516
#define RNN_SMEM ((H_ * 64 + 16 * ASTRIDE) * 4)  // 164096 B

__global__ __launch_bounds__(128, 1) void rnn_kernel(const float* __restrict__ Whh)
{
    extern __shared__ float sm[];
    float* Ws = sm;               // [512][64] Whh slice (stationary)
    float* As = sm + H_ * 64;     // [16][ASTRIDE] current h rows

    const int cta = blockIdx.x;
    const int mg  = cta >> 3;
    const int m0  = mg * 16;
    const int n0  = (cta & 7) * 64;
    const int t   = threadIdx.x;
    const int w   = t >> 5, l = t & 31;
    const int c4  = 4 * (l & 15);          // columns c4..c4+3
    const int rA  = 4 * w + 2 * (l >> 4);  // this thread: rows rA, rA+1
    const int rB  = rA + 1;

    // Load Whh[:, n0:n0+64] into smem once.
#pragma unroll 4
    for (int rep = 0; rep < 64; rep++) {
        int i4 = rep * 128 + t;
        int k  = i4 >> 4;
        int j4 = (i4 & 15) * 4;
        *(float4*)&Ws[k * 64 + j4] = *(const float4*)&Whh[(size_t)k * H_ + n0 + j4];
    }

    float4 psA = {0, 0, 0, 0}, psB = {0, 0, 0, 0};

    // prefetch P for step 0 (one LDG.128 per row)
    const size_t pstride = (size_t)B_ * H_;
    const size_t pbA = (size_t)(m0 + rA) * H_ + n0 + c4;
    const size_t pbB = (size_t)(m0 + rB) * H_ + n0 + c4;
    ulonglong2 pA = *(const ulonglong2*)&g_P[pbA];
    ulonglong2 pB = *(const ulonglong2*)&g_P[pbB];

    unsigned* bar = &g_bars[mg];
    int cur = 0;
    for (int step = 0; step < S_; step++) {
        const float* hsrc = g_h[cur];
#pragma unroll
        for (int rep = 0; rep < 16; rep++) {
            int i4  = rep * 128 + t;
            int row = i4 >> 7;
            int k4  = (i4 & 127) * 4;
            *(float4*)&As[row * ASTRIDE + k4] =
                *(const float4*)&hsrc[(size_t)(m0 + row) * H_ + k4];
        }
        __syncthreads();

        u64 aA0 = pA.x, aA1 = pA.y;
        u64 aB0 = pB.x, aB1 = pB.y;

        const float* apA = &As[rA * ASTRIDE];
        const float* apB = &As[rB * ASTRIDE];
        const float* wp  = &Ws[c4];
#pragma unroll 8
        for (int k = 0; k < H_; k += 4) {
            float4 A0 = *(const float4*)(apA + k);
            float4 A1 = *(const float4*)(apB + k);
#define RK2(comp) {                                             \
            ulonglong2 wv = *(const ulonglong2*)(wp); wp += 64; \
            u64 sA = splat2(A0.comp), sB = splat2(A1.comp);     \
            fma2(aA0, sA, wv.x); fma2(aA1, sA, wv.y);           \
            fma2(aB0, sB, wv.x); fma2(aB1, sB, wv.y); }
            RK2(x) RK2(y) RK2(z) RK2(w)
#undef RK2
        }

        float* hdst = g_h[cur ^ 1];
        {
            float2 v0 = u2f(aA0), v1 = u2f(aA1);
            float4 o;
            o.x = fmaxf(v0.x, 0.f); o.y = fmaxf(v0.y, 0.f);
            o.z = fmaxf(v1.x, 0.f); o.w = fmaxf(v1.y, 0.f);
            *(float4*)&hdst[pbA] = o;
            psA.x += o.x; psA.y += o.y; psA.z += o.z; psA.w += o.w;
        }
        {
            float2 v0 = u2f(aB0), v1 = u2f(aB1);
            float4 o;
            o.x = fmaxf(v0.x, 0.f); o.y = fmaxf(v0.y, 0.f);
            o.z = fmaxf(v1.x, 0.f); o.w = fmaxf(v1.y, 0.f);
            *(float4*)&hdst[pbB] = o;
            psB.x += o.x; psB.y += o.y; psB.z += o.z; psB.w += o.w;
        }

        if (step + 1 < S_) {
            // prefetch next step's P (no recurrence dependency) before the spin
            const size_t po = (size_t)(step + 1) * pstride;
            pA = *(const ulonglong2*)&g_P[pbA + po];
            pB = *(const ulonglong2*)&g_P[pbB + po];

            __syncthreads();
            if (t == 0) {
                asm volatile("red.release.gpu.add.u32 [%0], 1;" :: "l"(bar) : "memory");
                unsigned v8, target = 8u * (unsigned)(step + 1);
                do {
                    asm volatile("ld.acquire.gpu.u32 %0, [%1];" : "=r"(v8) : "l"(bar) : "memory");
                } while (v8 < target);
            }
            __syncthreads();
        }
        cur ^= 1;
    }

    const float inv = 1.0f / (float)S_;
    float4 q;
    q.x = psA.x * inv; q.y = psA.y * inv; q.z = psA.z * inv; q.w = psA.w * inv;
    *(float4*)&g_pool[pbA] = q;
    q.x = psB.x * inv; q.y = psB.y * inv; q.z = psB.z * inv; q.w = psB.w * inv;
    *(float4*)&g_pool[pbB] = q;
}

// ============================================================================
// Kernel C: out = pooled @ Wfc + bfc
// ============================================================================
__global__ __launch_bounds__(128) void fc_kernel(const float* __restrict__ Wfc,
                                                 const float* __restrict__ bfc,
                                                 float* __restrict__ out)
{
    const int b = blockIdx.x;
    const int t = threadIdx.x;
    float s0 = 0, s1 = 0, s2 = 0, s3 = 0;
    const float* pr = &g_pool[(size_t)b * H_];
    for (int k = t; k < H_; k += 128) {
        float v = pr[k];
        float4 wv = *(const float4*)&Wfc[k * 4];
        s0 += v * wv.x; s1 += v * wv.y; s2 += v * wv.z; s3 += v * wv.w;
    }
#pragma unroll
    for (int o = 16; o > 0; o >>= 1) {
        s0 += __shfl_down_sync(0xffffffffu, s0, o);
        s1 += __shfl_down_sync(0xffffffffu, s1, o);
        s2 += __shfl_down_sync(0xffffffffu, s2, o);
        s3 += __shfl_down_sync(0xffffffffu, s3, o);
    }
    __shared__ float red[4][4];
    if ((t & 31) == 0) {
        int wrp = t >> 5;
        red[wrp][0] = s0; red[wrp][1] = s1; red[wrp][2] = s2; red[wrp][3] = s3;
    }
    __syncthreads();
    if (t < 4) {
        out[b * 4 + t] = red[0][t] + red[1][t] + red[2][t] + red[3][t] + bfc[t];
    }
}

// ============================================================================
extern "C" void kernel_launch(void* const* d_in, const int* in_sizes, int n_in,
                              void* d_out, int out_size)
{
    const int*   x   = (const int*)d_in[0];
    const float* emb = (const float*)d_in[1];
    const float* Wxh = (const float*)d_in[2];
    const float* bxh = (const float*)d_in[3];
    const float* Whh = (const float*)d_in[4];
    const float* bhh = (const float*)d_in[5];
    const float* Wfc = (const float*)d_in[6];
    const float* bfc = (const float*)d_in[7];
    float* out = (float*)d_out;

    void *hAddr = nullptr, *barAddr = nullptr;
    cudaGetSymbolAddress(&hAddr, g_h);
    cudaGetSymbolAddress(&barAddr, g_bars);
    cudaMemsetAsync(hAddr, 0, sizeof(float) * 2 * B_ * H_);
    cudaMemsetAsync(barAddr, 0, sizeof(unsigned) * 16);

    cudaFuncSetAttribute(precompute_kernel, cudaFuncAttributeMaxDynamicSharedMemorySize, PC_SMEM);
    cudaFuncSetAttribute(rnn_kernel, cudaFuncAttributeMaxDynamicSharedMemorySize, RNN_SMEM);

    precompute_kernel<<<dim3(4, 800), 256, PC_SMEM>>>(x, emb, Wxh, bxh, bhh);
    rnn_kernel<<<128, 128, RNN_SMEM>>>(Whh);
    fc_kernel<<<B_, 128>>>(Wfc, bfc, out);
}